// round 5
// baseline (speedup 1.0000x reference)
#include <cuda_runtime.h>
#include <cuda_bf16.h>
#include <mma.h>
#include <cstdint>
#include <cstddef>

using namespace nvcuda;

#define N_NODES 50000
#define N_NODES_PAD 50048          // 391 tiles * 128
#define N_EDGES 800000
#define HDIM 128
#define LN_EPS 1e-5f
#define LDS_PAD 136                // padded leading dim (floats), mult of 8
#define NP_PAD 264                 // nodeproj B leading dim (256+8)
#define N_TILES (N_EDGES / 128)
#define NP_TILES ((N_NODES + 127) / 128)

// Scratch (allocation-free rule: __device__ globals)
__device__ float g_xsxr[(size_t)N_NODES_PAD * 256];  // [n,0:128]=x@Ws, [n,128:256]=x@Wr
__device__ float g_aggr[(size_t)N_NODES * HDIM];

__device__ __forceinline__ float t32(float v) { return wmma::__float_to_tf32(v); }

__device__ __forceinline__ void red_add_v4(float* p, float a, float b, float c, float d) {
    asm volatile("red.global.add.v4.f32 [%0], {%1, %2, %3, %4};"
                 :: "l"(p), "f"(a), "f"(b), "f"(c), "f"(d) : "memory");
}

typedef wmma::fragment<wmma::matrix_a, 16, 16, 8, wmma::precision::tf32, wmma::row_major> FragA;
typedef wmma::fragment<wmma::matrix_b, 16, 16, 8, wmma::precision::tf32, wmma::row_major> FragB;
typedef wmma::fragment<wmma::accumulator, 16, 16, 8, float> FragC;

// ---------------------------------------------------------------------------
// Node projection (persistent): XsXr[tile] = x[tile] @ [Ws | Wr]  (+0 bias)
// CTA: 256 thr = 8 warps, warp grid 2x4, 64x64 per warp over 128x256.
// B = [Ws | Wr] as row-major [k=128][n=256] stays smem-resident.
// C stored straight to global (g_xsxr padded to 50048 rows).
// ---------------------------------------------------------------------------
__global__ __launch_bounds__(256, 1)
void nodeproj_kernel(const float* __restrict__ x, const float* __restrict__ W1) {
    extern __shared__ float sm[];
    float* sB = sm;                     // 128 x NP_PAD
    float* sA = sm + 128 * NP_PAD;      // 128 x LDS_PAD

    const int tid = threadIdx.x;
    const int w = tid >> 5;
    const int wr = w >> 2;              // 0..1 : 64-row strip
    const int wc = w & 3;               // 0..3 : 64-col strip

    // stage B: n<128 -> W1[k][n] (Ws), n>=128 -> W1[128+k][n-128] (Wr)
    for (int idx = tid; idx < 128 * 64; idx += 256) {
        int k = idx >> 6, c4 = idx & 63;
        const float* srcrow = (c4 < 32)
            ? (W1 + (size_t)k * HDIM + c4 * 4)
            : (W1 + (size_t)(128 + k) * HDIM + (c4 - 32) * 4);
        float4 v = *(const float4*)srcrow;
        float* d = sB + k * NP_PAD + c4 * 4;
        d[0] = t32(v.x); d[1] = t32(v.y); d[2] = t32(v.z); d[3] = t32(v.w);
    }
    __syncthreads();

    for (int t = blockIdx.x; t < NP_TILES; t += gridDim.x) {
        const int rowBase = t * 128;

        for (int idx = tid; idx < 128 * 32; idx += 256) {
            int r = idx >> 5, c4 = idx & 31;
            int gr = rowBase + r;
            float4 v = make_float4(0.f, 0.f, 0.f, 0.f);
            if (gr < N_NODES) v = ((const float4*)(x + (size_t)gr * HDIM))[c4];
            float* d = sA + r * LDS_PAD + c4 * 4;
            d[0] = t32(v.x); d[1] = t32(v.y); d[2] = t32(v.z); d[3] = t32(v.w);
        }
        __syncthreads();

        FragC acc[4][4];
        #pragma unroll
        for (int i = 0; i < 4; ++i)
            #pragma unroll
            for (int j = 0; j < 4; ++j) wmma::fill_fragment(acc[i][j], 0.f);

        #pragma unroll
        for (int kk = 0; kk < 16; ++kk) {
            FragA a[4]; FragB b[4];
            #pragma unroll
            for (int i = 0; i < 4; ++i)
                wmma::load_matrix_sync(a[i], sA + (wr * 64 + i * 16) * LDS_PAD + kk * 8, LDS_PAD);
            #pragma unroll
            for (int j = 0; j < 4; ++j)
                wmma::load_matrix_sync(b[j], sB + (kk * 8) * NP_PAD + wc * 64 + j * 16, NP_PAD);
            #pragma unroll
            for (int i = 0; i < 4; ++i)
                #pragma unroll
                for (int j = 0; j < 4; ++j) wmma::mma_sync(acc[i][j], a[i], b[j], acc[i][j]);
        }

        // store direct to global (rows beyond N_NODES land in the pad region)
        #pragma unroll
        for (int i = 0; i < 4; ++i)
            #pragma unroll
            for (int j = 0; j < 4; ++j)
                wmma::store_matrix_sync(
                    g_xsxr + (size_t)(rowBase + wr * 64 + i * 16) * 256 + wc * 64 + j * 16,
                    acc[i][j], 256, wmma::mem_row_major);
        __syncthreads();   // all frag reads of sA done before next staging
    }
}

// ---------------------------------------------------------------------------
// Fused edge kernel: 256 thr = 2 warpgroups, each wg = 4 warps (one/SMSP)
// pipelining its own 128-edge tile (own A buffer) against the other wg.
// Warp tile 64x64 (2x2 grid).  msg = relu(ef@We + Xs[s] + Xr[r] + b),
// scattered with red.global.add.v4 into g_aggr[receiver].
// ---------------------------------------------------------------------------
__global__ __launch_bounds__(256, 1)
void edge_kernel(const float* __restrict__ ef,
                 const int* __restrict__ senders,
                 const int* __restrict__ receivers,
                 const float* __restrict__ W1,
                 const float* __restrict__ b1) {
    extern __shared__ float sm[];
    float* sBias = sm;                       // 128 floats
    float* sB  = sm + 128;                   // 128 x LDS_PAD (We, tf32)
    float* sA0 = sB + 128 * LDS_PAD;         // wg0 tile / C buffer
    float* sA1 = sA0 + 128 * LDS_PAD;        // wg1

    const int tid = threadIdx.x;
    const int wg = tid >> 7;                 // 0/1
    const int wg_tid = tid & 127;
    const int w4 = (tid >> 5) & 3;           // warp within wg
    const int wr = w4 >> 1;                  // 0..1 row strip (64)
    const int wc = w4 & 1;                   // 0..1 col strip (64)
    float* sA = wg ? sA1 : sA0;

    if (tid < 128) sBias[tid] = b1[tid];
    // stage B = We (row-major k x n): B[k][n] = W1[256+k][n]
    for (int idx = tid; idx < 128 * 32; idx += 256) {
        int k = idx >> 5, c4 = idx & 31;
        float4 v = *(const float4*)(W1 + (size_t)(256 + k) * HDIM + c4 * 4);
        float* d = sB + k * LDS_PAD + c4 * 4;
        d[0] = t32(v.x); d[1] = t32(v.y); d[2] = t32(v.z); d[3] = t32(v.w);
    }
    __syncthreads();

    const float4* bias4 = (const float4*)sBias;
    const int barid = wg + 1;

    for (int t = blockIdx.x * 2 + wg; t < N_TILES; t += 2 * gridDim.x) {
        // --- stage A: 128 edges x 128 feats (tf32-rounded) ---
        const float4* src = (const float4*)(ef + (size_t)t * (128 * HDIM));
        #pragma unroll
        for (int i = 0; i < 32; ++i) {
            int f = i * 128 + wg_tid;
            int r = f >> 5, c4 = f & 31;
            float4 v = src[f];
            float* d = sA + r * LDS_PAD + c4 * 4;
            d[0] = t32(v.x); d[1] = t32(v.y); d[2] = t32(v.z); d[3] = t32(v.w);
        }
        asm volatile("bar.sync %0, 128;" :: "r"(barid) : "memory");

        // --- 128x128x128 tf32 MMA, 64x64 per warp ---
        FragC acc[4][4];
        #pragma unroll
        for (int i = 0; i < 4; ++i)
            #pragma unroll
            for (int j = 0; j < 4; ++j) wmma::fill_fragment(acc[i][j], 0.f);

        #pragma unroll
        for (int kk = 0; kk < 16; ++kk) {
            FragA a[4]; FragB b[4];
            #pragma unroll
            for (int i = 0; i < 4; ++i)
                wmma::load_matrix_sync(a[i], sA + (wr * 64 + i * 16) * LDS_PAD + kk * 8, LDS_PAD);
            #pragma unroll
            for (int j = 0; j < 4; ++j)
                wmma::load_matrix_sync(b[j], sB + (kk * 8) * LDS_PAD + wc * 64 + j * 16, LDS_PAD);
            #pragma unroll
            for (int i = 0; i < 4; ++i)
                #pragma unroll
                for (int j = 0; j < 4; ++j) wmma::mma_sync(acc[i][j], a[i], b[j], acc[i][j]);
        }
        asm volatile("bar.sync %0, 128;" :: "r"(barid) : "memory");

        // --- C -> smem (reuse sA) ---
        #pragma unroll
        for (int i = 0; i < 4; ++i)
            #pragma unroll
            for (int j = 0; j < 4; ++j)
                wmma::store_matrix_sync(sA + (wr * 64 + i * 16) * LDS_PAD + wc * 64 + j * 16,
                                        acc[i][j], LDS_PAD, wmma::mem_row_major);
        asm volatile("bar.sync %0, 128;" :: "r"(barid) : "memory");

        // --- epilogue: one thread per edge row ---
        const int e = t * 128 + wg_tid;
        const int s = senders[e];
        const int rc = receivers[e];
        const float4* xs = (const float4*)(g_xsxr + (size_t)s * 256);
        const float4* xr = (const float4*)(g_xsxr + (size_t)rc * 256 + 128);
        const float4* ac = (const float4*)(sA + wg_tid * LDS_PAD);
        float* dst = g_aggr + (size_t)rc * HDIM;

        #pragma unroll
        for (int c4 = 0; c4 < 32; ++c4) {
            float4 m = ac[c4];
            float4 a_ = xs[c4];
            float4 r_ = xr[c4];
            float4 bb = bias4[c4];
            float vx = fmaxf(m.x + a_.x + r_.x + bb.x, 0.f);
            float vy = fmaxf(m.y + a_.y + r_.y + bb.y, 0.f);
            float vz = fmaxf(m.z + a_.z + r_.z + bb.z, 0.f);
            float vw = fmaxf(m.w + a_.w + r_.w + bb.w, 0.f);
            red_add_v4(dst + c4 * 4, vx, vy, vz, vw);
        }
        asm volatile("bar.sync %0, 128;" :: "r"(barid) : "memory");  // before next staging
    }
}

// ---------------------------------------------------------------------------
// LayerNorm: out = gamma * (h - mu) * rsqrt(var + eps) + beta, h = aggr + x
// ---------------------------------------------------------------------------
__global__ __launch_bounds__(256)
void ln_kernel(const float* __restrict__ x,
               const float* __restrict__ gamma,
               const float* __restrict__ beta,
               float* __restrict__ out) {
    const int gwarp = (blockIdx.x * blockDim.x + threadIdx.x) >> 5;
    const int lane = threadIdx.x & 31;
    if (gwarp >= N_NODES) return;

    const int c = lane * 4;
    float4 ag = *(const float4*)(g_aggr + (size_t)gwarp * HDIM + c);
    float4 xv = *(const float4*)(x + (size_t)gwarp * HDIM + c);
    float4 h = make_float4(ag.x + xv.x, ag.y + xv.y, ag.z + xv.z, ag.w + xv.w);

    float s = h.x + h.y + h.z + h.w;
    float ss = h.x * h.x + h.y * h.y + h.z * h.z + h.w * h.w;
    #pragma unroll
    for (int off = 16; off > 0; off >>= 1) {
        s += __shfl_xor_sync(0xffffffff, s, off);
        ss += __shfl_xor_sync(0xffffffff, ss, off);
    }
    const float mean = s * (1.f / HDIM);
    const float var = ss * (1.f / HDIM) - mean * mean;
    const float inv = rsqrtf(var + LN_EPS);

    float4 g = *(const float4*)(gamma + c);
    float4 b = *(const float4*)(beta + c);
    float4 o;
    o.x = g.x * (h.x - mean) * inv + b.x;
    o.y = g.y * (h.y - mean) * inv + b.y;
    o.z = g.z * (h.z - mean) * inv + b.z;
    o.w = g.w * (h.w - mean) * inv + b.w;
    *(float4*)(out + (size_t)gwarp * HDIM + c) = o;
}

// ---------------------------------------------------------------------------
extern "C" void kernel_launch(void* const* d_in, const int* in_sizes, int n_in,
                              void* d_out, int out_size) {
    const float* x         = (const float*)d_in[0];
    const int*   senders   = (const int*)d_in[1];
    const int*   receivers = (const int*)d_in[2];
    const float* ef        = (const float*)d_in[3];
    const float* W1        = (const float*)d_in[4];
    const float* b1        = (const float*)d_in[5];
    const float* gamma     = (const float*)d_in[6];
    const float* beta      = (const float*)d_in[7];
    float* out = (float*)d_out;

    void* aggr_ptr = nullptr;
    cudaGetSymbolAddress(&aggr_ptr, g_aggr);
    cudaMemsetAsync(aggr_ptr, 0, (size_t)N_NODES * HDIM * sizeof(float), 0);

    const size_t smem_np = (size_t)(128 * NP_PAD + 128 * LDS_PAD) * sizeof(float);       // ~200 KB
    const size_t smem_ed = (size_t)(128 + 3 * 128 * LDS_PAD) * sizeof(float);            // ~205 KB
    cudaFuncSetAttribute(nodeproj_kernel, cudaFuncAttributeMaxDynamicSharedMemorySize, (int)smem_np);
    cudaFuncSetAttribute(edge_kernel, cudaFuncAttributeMaxDynamicSharedMemorySize, (int)smem_ed);

    nodeproj_kernel<<<148, 256, smem_np>>>(x, W1);
    edge_kernel<<<148, 256, smem_ed>>>(ef, senders, receivers, W1, b1);
    ln_kernel<<<(N_NODES + 7) / 8, 256>>>(x, gamma, beta, out);
}

// round 6
// speedup vs baseline: 1.4511x; 1.4511x over previous
#include <cuda_runtime.h>
#include <cuda_bf16.h>
#include <mma.h>
#include <cstdint>
#include <cstddef>

using namespace nvcuda;

#define N_NODES 50000
#define N_NODES_PAD 50048          // 391 tiles * 128
#define N_EDGES 800000
#define HDIM 128
#define LN_EPS 1e-5f
#define LDS_PAD 136                // A / edge-B leading dim (floats)
#define NP_PAD 264                 // nodeproj B leading dim (256+8)
#define N_TILES (N_EDGES / 128)
#define NP_TILES ((N_NODES + 127) / 128)

// Scratch (allocation-free rule: __device__ globals)
__device__ float g_xsxr[(size_t)N_NODES_PAD * 256];  // [n,0:128]=x@Ws, [n,128:256]=x@Wr
__device__ float g_aggr[(size_t)N_NODES * HDIM];

__device__ __forceinline__ float t32(float v) { return wmma::__float_to_tf32(v); }

__device__ __forceinline__ void red_add_v4(float* p, float a, float b, float c, float d) {
    asm volatile("red.global.add.v4.f32 [%0], {%1, %2, %3, %4};"
                 :: "l"(p), "f"(a), "f"(b), "f"(c), "f"(d) : "memory");
}

typedef wmma::fragment<wmma::matrix_a, 16, 16, 8, wmma::precision::tf32, wmma::row_major> FragA;
typedef wmma::fragment<wmma::matrix_b, 16, 16, 8, wmma::precision::tf32, wmma::row_major> FragB;
typedef wmma::fragment<wmma::accumulator, 16, 16, 8, float> FragC;

// ---------------------------------------------------------------------------
// Node projection (persistent): XsXr[tile] = x[tile] @ [Ws | Wr]
// 512 thr = 16 warps, 2x8 grid of 64x32 warp tiles over 128x256.
// B = [Ws | Wr] row-major [k=128][n=256] smem-resident; x staged once.
// ---------------------------------------------------------------------------
__global__ __launch_bounds__(512, 1)
void nodeproj_kernel(const float* __restrict__ x, const float* __restrict__ W1) {
    extern __shared__ float sm[];
    float* sB = sm;                     // 128 x NP_PAD
    float* sA = sm + 128 * NP_PAD;      // 128 x LDS_PAD

    const int tid = threadIdx.x;
    const int w = tid >> 5;
    const int wr = w >> 3;              // 0..1 : 64-row strip
    const int wc = w & 7;               // 0..7 : 32-col strip

    // stage B: n<128 -> W1[k][n] (Ws), n>=128 -> W1[128+k][n-128] (Wr)
    for (int idx = tid; idx < 128 * 64; idx += 512) {
        int k = idx >> 6, c4 = idx & 63;
        const float* srcrow = (c4 < 32)
            ? (W1 + (size_t)k * HDIM + c4 * 4)
            : (W1 + (size_t)(128 + k) * HDIM + (c4 - 32) * 4);
        float4 v = *(const float4*)srcrow;
        float* d = sB + k * NP_PAD + c4 * 4;
        d[0] = t32(v.x); d[1] = t32(v.y); d[2] = t32(v.z); d[3] = t32(v.w);
    }
    __syncthreads();

    for (int t = blockIdx.x; t < NP_TILES; t += gridDim.x) {
        const int rowBase = t * 128;

        for (int idx = tid; idx < 128 * 32; idx += 512) {
            int r = idx >> 5, c4 = idx & 31;
            int gr = rowBase + r;
            float4 v = make_float4(0.f, 0.f, 0.f, 0.f);
            if (gr < N_NODES) v = ((const float4*)(x + (size_t)gr * HDIM))[c4];
            float* d = sA + r * LDS_PAD + c4 * 4;
            d[0] = t32(v.x); d[1] = t32(v.y); d[2] = t32(v.z); d[3] = t32(v.w);
        }
        __syncthreads();

        FragC acc[4][2];
        #pragma unroll
        for (int i = 0; i < 4; ++i)
            #pragma unroll
            for (int j = 0; j < 2; ++j) wmma::fill_fragment(acc[i][j], 0.f);

        #pragma unroll
        for (int kk = 0; kk < 16; ++kk) {
            FragA a[4]; FragB b[2];
            #pragma unroll
            for (int i = 0; i < 4; ++i)
                wmma::load_matrix_sync(a[i], sA + (wr * 64 + i * 16) * LDS_PAD + kk * 8, LDS_PAD);
            #pragma unroll
            for (int j = 0; j < 2; ++j)
                wmma::load_matrix_sync(b[j], sB + (kk * 8) * NP_PAD + wc * 32 + j * 16, NP_PAD);
            #pragma unroll
            for (int i = 0; i < 4; ++i)
                #pragma unroll
                for (int j = 0; j < 2; ++j) wmma::mma_sync(acc[i][j], a[i], b[j], acc[i][j]);
        }

        // store direct to global (pad rows absorb the tail tile)
        #pragma unroll
        for (int i = 0; i < 4; ++i)
            #pragma unroll
            for (int j = 0; j < 2; ++j)
                wmma::store_matrix_sync(
                    g_xsxr + (size_t)(rowBase + wr * 64 + i * 16) * 256 + wc * 32 + j * 16,
                    acc[i][j], 256, wmma::mem_row_major);
        __syncthreads();
    }
}

// ---------------------------------------------------------------------------
// Fused edge kernel: 512 thr = 2 warpgroups of 8 warps. Each wg streams its
// OWN 128-edge tiles (own A/C smem, own named barrier), so one wg's memory
// phases overlap the other's MMA. Warp tile 64x32 (2x4 grid).
// msg = relu(ef@We + Xs[s] + Xr[r] + b) -> red.global.add.v4 into g_aggr[r].
// ---------------------------------------------------------------------------
__global__ __launch_bounds__(512, 1)
void edge_kernel(const float* __restrict__ ef,
                 const int* __restrict__ senders,
                 const int* __restrict__ receivers,
                 const float* __restrict__ W1,
                 const float* __restrict__ b1) {
    extern __shared__ float sm[];
    float* sBias = sm;                       // 128 floats
    float* sB  = sm + 128;                   // 128 x LDS_PAD (We, tf32)
    float* sA0 = sB + 128 * LDS_PAD;         // wg0 A / C buffer
    float* sA1 = sA0 + 128 * LDS_PAD;        // wg1

    const int tid = threadIdx.x;
    const int w = tid >> 5;
    const int wg = w >> 3;                   // 0/1
    const int wg_tid = tid & 255;
    const int w8 = w & 7;
    const int wr = w8 >> 2;                  // 0..1 : 64-row strip
    const int wc = w8 & 3;                   // 0..3 : 32-col strip
    float* sA = wg ? sA1 : sA0;

    if (tid < 128) sBias[tid] = b1[tid];
    // stage B = We (row-major k x n): B[k][n] = W1[256+k][n]
    for (int idx = tid; idx < 128 * 32; idx += 512) {
        int k = idx >> 5, c4 = idx & 31;
        float4 v = *(const float4*)(W1 + (size_t)(256 + k) * HDIM + c4 * 4);
        float* d = sB + k * LDS_PAD + c4 * 4;
        d[0] = t32(v.x); d[1] = t32(v.y); d[2] = t32(v.z); d[3] = t32(v.w);
    }
    __syncthreads();

    const float4* bias4 = (const float4*)sBias;
    const int barid = wg + 1;

    for (int t = blockIdx.x * 2 + wg; t < N_TILES; t += 2 * gridDim.x) {
        // --- stage A: 128 edges x 128 feats (tf32-rounded), 256 threads ---
        const float4* src = (const float4*)(ef + (size_t)t * (128 * HDIM));
        #pragma unroll
        for (int i = 0; i < 16; ++i) {
            int f = i * 256 + wg_tid;
            int r = f >> 5, c4 = f & 31;
            float4 v = src[f];
            float* d = sA + r * LDS_PAD + c4 * 4;
            d[0] = t32(v.x); d[1] = t32(v.y); d[2] = t32(v.z); d[3] = t32(v.w);
        }
        asm volatile("bar.sync %0, 256;" :: "r"(barid) : "memory");

        // --- 128x128x128 tf32 MMA, 64x32 per warp ---
        FragC acc[4][2];
        #pragma unroll
        for (int i = 0; i < 4; ++i)
            #pragma unroll
            for (int j = 0; j < 2; ++j) wmma::fill_fragment(acc[i][j], 0.f);

        #pragma unroll
        for (int kk = 0; kk < 16; ++kk) {
            FragA a[4]; FragB b[2];
            #pragma unroll
            for (int i = 0; i < 4; ++i)
                wmma::load_matrix_sync(a[i], sA + (wr * 64 + i * 16) * LDS_PAD + kk * 8, LDS_PAD);
            #pragma unroll
            for (int j = 0; j < 2; ++j)
                wmma::load_matrix_sync(b[j], sB + (kk * 8) * LDS_PAD + wc * 32 + j * 16, LDS_PAD);
            #pragma unroll
            for (int i = 0; i < 4; ++i)
                #pragma unroll
                for (int j = 0; j < 2; ++j) wmma::mma_sync(acc[i][j], a[i], b[j], acc[i][j]);
        }
        asm volatile("bar.sync %0, 256;" :: "r"(barid) : "memory");

        // --- C -> smem (reuse this wg's sA) ---
        #pragma unroll
        for (int i = 0; i < 4; ++i)
            #pragma unroll
            for (int j = 0; j < 2; ++j)
                wmma::store_matrix_sync(sA + (wr * 64 + i * 16) * LDS_PAD + wc * 32 + j * 16,
                                        acc[i][j], LDS_PAD, wmma::mem_row_major);
        asm volatile("bar.sync %0, 256;" :: "r"(barid) : "memory");

        // --- epilogue: 2 threads per edge row, 64 cols each ---
        {
            const int row = wg_tid >> 1;
            const int half = wg_tid & 1;
            const int e = t * 128 + row;
            const int s = senders[e];
            const int rc = receivers[e];
            const float4* xs = (const float4*)(g_xsxr + (size_t)s * 256) + half * 16;
            const float4* xr = (const float4*)(g_xsxr + (size_t)rc * 256 + 128) + half * 16;
            const float4* ac = (const float4*)(sA + row * LDS_PAD) + half * 16;
            const float4* bb4 = bias4 + half * 16;
            float* dst = g_aggr + (size_t)rc * HDIM + half * 64;

            #pragma unroll
            for (int j = 0; j < 16; ++j) {
                float4 m = ac[j];
                float4 a_ = xs[j];
                float4 r_ = xr[j];
                float4 bb = bb4[j];
                float vx = fmaxf(m.x + a_.x + r_.x + bb.x, 0.f);
                float vy = fmaxf(m.y + a_.y + r_.y + bb.y, 0.f);
                float vz = fmaxf(m.z + a_.z + r_.z + bb.z, 0.f);
                float vw = fmaxf(m.w + a_.w + r_.w + bb.w, 0.f);
                red_add_v4(dst + j * 4, vx, vy, vz, vw);
            }
        }
        asm volatile("bar.sync %0, 256;" :: "r"(barid) : "memory");  // before next staging
    }
}

// ---------------------------------------------------------------------------
// LayerNorm: out = gamma * (h - mu) * rsqrt(var + eps) + beta, h = aggr + x
// ---------------------------------------------------------------------------
__global__ __launch_bounds__(256)
void ln_kernel(const float* __restrict__ x,
               const float* __restrict__ gamma,
               const float* __restrict__ beta,
               float* __restrict__ out) {
    const int gwarp = (blockIdx.x * blockDim.x + threadIdx.x) >> 5;
    const int lane = threadIdx.x & 31;
    if (gwarp >= N_NODES) return;

    const int c = lane * 4;
    float4 ag = *(const float4*)(g_aggr + (size_t)gwarp * HDIM + c);
    float4 xv = *(const float4*)(x + (size_t)gwarp * HDIM + c);
    float4 h = make_float4(ag.x + xv.x, ag.y + xv.y, ag.z + xv.z, ag.w + xv.w);

    float s = h.x + h.y + h.z + h.w;
    float ss = h.x * h.x + h.y * h.y + h.z * h.z + h.w * h.w;
    #pragma unroll
    for (int off = 16; off > 0; off >>= 1) {
        s += __shfl_xor_sync(0xffffffff, s, off);
        ss += __shfl_xor_sync(0xffffffff, ss, off);
    }
    const float mean = s * (1.f / HDIM);
    const float var = ss * (1.f / HDIM) - mean * mean;
    const float inv = rsqrtf(var + LN_EPS);

    float4 g = *(const float4*)(gamma + c);
    float4 b = *(const float4*)(beta + c);
    float4 o;
    o.x = g.x * (h.x - mean) * inv + b.x;
    o.y = g.y * (h.y - mean) * inv + b.y;
    o.z = g.z * (h.z - mean) * inv + b.z;
    o.w = g.w * (h.w - mean) * inv + b.w;
    *(float4*)(out + (size_t)gwarp * HDIM + c) = o;
}

// ---------------------------------------------------------------------------
extern "C" void kernel_launch(void* const* d_in, const int* in_sizes, int n_in,
                              void* d_out, int out_size) {
    const float* x         = (const float*)d_in[0];
    const int*   senders   = (const int*)d_in[1];
    const int*   receivers = (const int*)d_in[2];
    const float* ef        = (const float*)d_in[3];
    const float* W1        = (const float*)d_in[4];
    const float* b1        = (const float*)d_in[5];
    const float* gamma     = (const float*)d_in[6];
    const float* beta      = (const float*)d_in[7];
    float* out = (float*)d_out;

    void* aggr_ptr = nullptr;
    cudaGetSymbolAddress(&aggr_ptr, g_aggr);
    cudaMemsetAsync(aggr_ptr, 0, (size_t)N_NODES * HDIM * sizeof(float), 0);

    const size_t smem_np = (size_t)(128 * NP_PAD + 128 * LDS_PAD) * sizeof(float);   // ~200 KB
    const size_t smem_ed = (size_t)(128 + 3 * 128 * LDS_PAD) * sizeof(float);        // ~205 KB
    cudaFuncSetAttribute(nodeproj_kernel, cudaFuncAttributeMaxDynamicSharedMemorySize, (int)smem_np);
    cudaFuncSetAttribute(edge_kernel, cudaFuncAttributeMaxDynamicSharedMemorySize, (int)smem_ed);

    nodeproj_kernel<<<148, 512, smem_np>>>(x, W1);
    edge_kernel<<<148, 512, smem_ed>>>(ef, senders, receivers, W1, b1);
    ln_kernel<<<(N_NODES + 7) / 8, 256>>>(x, gamma, beta, out);
}

// round 8
// speedup vs baseline: 1.8869x; 1.3003x over previous
#include <cuda_runtime.h>
#include <cuda_bf16.h>
#include <mma.h>
#include <cstdint>
#include <cstddef>

#define N_NODES 50000
#define N_NODES_PAD 50048          // 391 tiles * 128
#define N_EDGES 800000
#define HDIM 128
#define LN_EPS 1e-5f
#define SAW 132                    // A smem stride in floats (132 % 32 == 4)
#define N_TILES (N_EDGES / 128)
#define NP_TILES ((N_NODES + 127) / 128)

// Scratch (allocation-free rule: __device__ globals)
__device__ float g_xsxr[(size_t)N_NODES_PAD * 256];  // [n,0:128]=x@Ws, [n,128:256]=x@Wr
__device__ float g_aggr[(size_t)N_NODES * HDIM];

__device__ __forceinline__ float t32(float v) { return nvcuda::wmma::__float_to_tf32(v); }

__device__ __forceinline__ void red_add_v4(float* p, float a, float b, float c, float d) {
    asm volatile("red.global.add.v4.f32 [%0], {%1, %2, %3, %4};"
                 :: "l"(p), "f"(a), "f"(b), "f"(c), "f"(d) : "memory");
}

__device__ __forceinline__ void mma_16n8k8(float* c, const uint32_t* a, const uint32_t* b) {
    asm volatile(
        "mma.sync.aligned.m16n8k8.row.col.f32.tf32.tf32.f32 "
        "{%0,%1,%2,%3}, {%4,%5,%6,%7}, {%8,%9}, {%0,%1,%2,%3};"
        : "+f"(c[0]), "+f"(c[1]), "+f"(c[2]), "+f"(c[3])
        : "r"(a[0]), "r"(a[1]), "r"(a[2]), "r"(a[3]), "r"(b[0]), "r"(b[1]));
}

// B fragment-major staging: value (k,n) of a [K=128][n] weight block.
// frag block (ks=k>>3, nt=n>>3) is 64 floats: lane = (n&7)*4 + (k&3), reg = (k&7)>>2.
__device__ __forceinline__ int bfrag_off(int k, int n, int NT) {
    int ks = k >> 3, nt = n >> 3;
    int lane = ((n & 7) << 2) | (k & 3);
    int reg = (k & 7) >> 2;
    return ((ks * NT + nt) << 6) + lane * 2 + reg;
}

// ---------------------------------------------------------------------------
// Node projection (persistent): XsXr[tile] = x[tile] @ [Ws | Wr]
// 512 thr = 16 warps, 2x8 grid of 64x32 warp tiles over 128x256.
// ---------------------------------------------------------------------------
__global__ __launch_bounds__(512, 1)
void nodeproj_kernel(const float* __restrict__ x, const float* __restrict__ W1) {
    extern __shared__ float sm[];
    float* sB = sm;                      // 16 ks * 32 nt * 64 = 32768 floats (frag-major)
    float* sA = sm + 32768;              // 128 x SAW

    const int tid = threadIdx.x;
    const int w = tid >> 5;
    const int lane = tid & 31;
    const int wr = w >> 3;               // 0..1 : 64-row strip
    const int wc = w & 7;                // 0..7 : 32-col strip

    // stage B frag-major: n<128 -> Ws=W1[k][n], n>=128 -> Wr=W1[128+k][n-128]
    for (int idx = tid; idx < 128 * 256; idx += 512) {
        int k = idx >> 8, n = idx & 255;
        float v = (n < 128) ? W1[(size_t)k * HDIM + n]
                            : W1[(size_t)(128 + k) * HDIM + (n - 128)];
        sB[bfrag_off(k, n, 32)] = t32(v);
    }
    __syncthreads();

    const float2* pB = (const float2*)sB;
    const float* Abase = sA + (wr * 64 + (lane >> 2)) * SAW + (lane & 3);

    for (int t = blockIdx.x; t < NP_TILES; t += gridDim.x) {
        const int rowBase = t * 128;

        for (int idx = tid; idx < 128 * 32; idx += 512) {
            int r = idx >> 5, c4 = idx & 31;
            int gr = rowBase + r;
            float4 v = make_float4(0.f, 0.f, 0.f, 0.f);
            if (gr < N_NODES) v = ((const float4*)(x + (size_t)gr * HDIM))[c4];
            float* d = sA + r * SAW + c4 * 4;
            d[0] = t32(v.x); d[1] = t32(v.y); d[2] = t32(v.z); d[3] = t32(v.w);
        }
        __syncthreads();

        float acc[4][4][4];
        #pragma unroll
        for (int i = 0; i < 4; ++i)
            #pragma unroll
            for (int j = 0; j < 4; ++j)
                acc[i][j][0] = acc[i][j][1] = acc[i][j][2] = acc[i][j][3] = 0.f;

        #pragma unroll
        for (int ks = 0; ks < 16; ++ks) {
            uint32_t a[4][4], b[4][2];
            #pragma unroll
            for (int i = 0; i < 4; ++i) {
                const float* p = Abase + i * (16 * SAW) + ks * 8;
                a[i][0] = __float_as_uint(p[0]);
                a[i][1] = __float_as_uint(p[8 * SAW]);
                a[i][2] = __float_as_uint(p[4]);
                a[i][3] = __float_as_uint(p[8 * SAW + 4]);
            }
            #pragma unroll
            for (int j = 0; j < 4; ++j) {
                float2 bb = pB[(ks * 32 + wc * 4 + j) * 32 + lane];
                b[j][0] = __float_as_uint(bb.x);
                b[j][1] = __float_as_uint(bb.y);
            }
            #pragma unroll
            for (int i = 0; i < 4; ++i)
                #pragma unroll
                for (int j = 0; j < 4; ++j) mma_16n8k8(acc[i][j], a[i], b[j]);
        }

        // store C straight to global (pad rows absorb the tail tile)
        #pragma unroll
        for (int i = 0; i < 4; ++i) {
            int row = rowBase + wr * 64 + i * 16 + (lane >> 2);
            #pragma unroll
            for (int j = 0; j < 4; ++j) {
                int col = wc * 32 + j * 8 + 2 * (lane & 3);
                *(float2*)(g_xsxr + (size_t)row * 256 + col) =
                    make_float2(acc[i][j][0], acc[i][j][1]);
                *(float2*)(g_xsxr + (size_t)(row + 8) * 256 + col) =
                    make_float2(acc[i][j][2], acc[i][j][3]);
            }
        }
        __syncthreads();
    }
}

// ---------------------------------------------------------------------------
// Fused edge kernel: 512 thr = 2 warpgroups of 8 warps, each wg streams its
// own 128-edge tiles (own A/C buffer + named barrier). Warp tile 64x32.
// msg = relu(ef@We + Xs[s] + Xr[r] + b) -> red.global.add.v4 into g_aggr[r].
// ---------------------------------------------------------------------------
__global__ __launch_bounds__(512, 1)
void edge_kernel(const float* __restrict__ ef,
                 const int* __restrict__ senders,
                 const int* __restrict__ receivers,
                 const float* __restrict__ W1,
                 const float* __restrict__ b1) {
    extern __shared__ float sm[];
    float* sBias = sm;                       // 128
    float* sB  = sm + 128;                   // 16 ks * 16 nt * 64 = 16384 (frag-major)
    float* sA0 = sB + 16384;                 // 128 x SAW (wg0 A / C)
    float* sA1 = sA0 + 128 * SAW;            // wg1

    const int tid = threadIdx.x;
    const int w = tid >> 5;
    const int lane = tid & 31;
    const int wg = w >> 3;                   // 0/1
    const int wg_tid = tid & 255;
    const int w8 = w & 7;
    const int wr = w8 >> 2;                  // 0..1 : 64-row strip
    const int wc = w8 & 3;                   // 0..3 : 32-col strip
    float* sA = wg ? sA1 : sA0;

    if (tid < 128) sBias[tid] = b1[tid];
    // stage B = We frag-major: B[k][n] = W1[256+k][n]
    for (int idx = tid; idx < 128 * 128; idx += 512) {
        int k = idx >> 7, n = idx & 127;
        sB[bfrag_off(k, n, 16)] = t32(W1[(size_t)(256 + k) * HDIM + n]);
    }
    __syncthreads();

    const float2* pB = (const float2*)sB;
    const float* Abase = sA + (wr * 64 + (lane >> 2)) * SAW + (lane & 3);
    const float4* bias4 = (const float4*)sBias;
    const int barid = wg + 1;

    for (int t = blockIdx.x * 2 + wg; t < N_TILES; t += 2 * gridDim.x) {
        // --- stage A: 128 edges x 128 feats (tf32-rounded), 256 threads ---
        const float4* src = (const float4*)(ef + (size_t)t * (128 * HDIM));
        #pragma unroll
        for (int i = 0; i < 16; ++i) {
            int f = i * 256 + wg_tid;
            int r = f >> 5, c4 = f & 31;
            float4 v = src[f];
            float* d = sA + r * SAW + c4 * 4;
            d[0] = t32(v.x); d[1] = t32(v.y); d[2] = t32(v.z); d[3] = t32(v.w);
        }
        asm volatile("bar.sync %0, 256;" :: "r"(barid) : "memory");

        // --- 128x128x128 tf32 MMA, 64x32 per warp, explicit m16n8k8 ---
        float acc[4][4][4];
        #pragma unroll
        for (int i = 0; i < 4; ++i)
            #pragma unroll
            for (int j = 0; j < 4; ++j)
                acc[i][j][0] = acc[i][j][1] = acc[i][j][2] = acc[i][j][3] = 0.f;

        #pragma unroll
        for (int ks = 0; ks < 16; ++ks) {
            uint32_t a[4][4], b[4][2];
            #pragma unroll
            for (int i = 0; i < 4; ++i) {
                const float* p = Abase + i * (16 * SAW) + ks * 8;
                a[i][0] = __float_as_uint(p[0]);
                a[i][1] = __float_as_uint(p[8 * SAW]);
                a[i][2] = __float_as_uint(p[4]);
                a[i][3] = __float_as_uint(p[8 * SAW + 4]);
            }
            #pragma unroll
            for (int j = 0; j < 4; ++j) {
                float2 bb = pB[(ks * 16 + wc * 4 + j) * 32 + lane];
                b[j][0] = __float_as_uint(bb.x);
                b[j][1] = __float_as_uint(bb.y);
            }
            #pragma unroll
            for (int i = 0; i < 4; ++i)
                #pragma unroll
                for (int j = 0; j < 4; ++j) mma_16n8k8(acc[i][j], a[i], b[j]);
        }
        asm volatile("bar.sync %0, 256;" :: "r"(barid) : "memory");

        // --- C -> smem (reuse this wg's sA) ---
        #pragma unroll
        for (int i = 0; i < 4; ++i) {
            int row = wr * 64 + i * 16 + (lane >> 2);
            #pragma unroll
            for (int j = 0; j < 4; ++j) {
                int col = wc * 32 + j * 8 + 2 * (lane & 3);
                *(float2*)(sA + row * SAW + col) = make_float2(acc[i][j][0], acc[i][j][1]);
                *(float2*)(sA + (row + 8) * SAW + col) = make_float2(acc[i][j][2], acc[i][j][3]);
            }
        }
        asm volatile("bar.sync %0, 256;" :: "r"(barid) : "memory");

        // --- epilogue: 2 threads per edge row, 64 cols each ---
        {
            const int row = wg_tid >> 1;
            const int half = wg_tid & 1;
            const int e = t * 128 + row;
            const int s = senders[e];
            const int rc = receivers[e];
            const float4* xs = (const float4*)(g_xsxr + (size_t)s * 256) + half * 16;
            const float4* xr = (const float4*)(g_xsxr + (size_t)rc * 256 + 128) + half * 16;
            const float4* ac = (const float4*)(sA + row * SAW) + half * 16;
            const float4* bb4 = bias4 + half * 16;
            float* dst = g_aggr + (size_t)rc * HDIM + half * 64;

            #pragma unroll
            for (int j = 0; j < 16; ++j) {
                float4 m = ac[j];
                float4 a_ = xs[j];
                float4 r_ = xr[j];
                float4 bb = bb4[j];
                float vx = fmaxf(m.x + a_.x + r_.x + bb.x, 0.f);
                float vy = fmaxf(m.y + a_.y + r_.y + bb.y, 0.f);
                float vz = fmaxf(m.z + a_.z + r_.z + bb.z, 0.f);
                float vw = fmaxf(m.w + a_.w + r_.w + bb.w, 0.f);
                red_add_v4(dst + j * 4, vx, vy, vz, vw);
            }
        }
        asm volatile("bar.sync %0, 256;" :: "r"(barid) : "memory");  // before next staging
    }
}

// ---------------------------------------------------------------------------
// LayerNorm: out = gamma * (h - mu) * rsqrt(var + eps) + beta, h = aggr + x
// ---------------------------------------------------------------------------
__global__ __launch_bounds__(256)
void ln_kernel(const float* __restrict__ x,
               const float* __restrict__ gamma,
               const float* __restrict__ beta,
               float* __restrict__ out) {
    const int gwarp = (blockIdx.x * blockDim.x + threadIdx.x) >> 5;
    const int lane = threadIdx.x & 31;
    if (gwarp >= N_NODES) return;

    const int c = lane * 4;
    float4 ag = *(const float4*)(g_aggr + (size_t)gwarp * HDIM + c);
    float4 xv = *(const float4*)(x + (size_t)gwarp * HDIM + c);
    float4 h = make_float4(ag.x + xv.x, ag.y + xv.y, ag.z + xv.z, ag.w + xv.w);

    float s = h.x + h.y + h.z + h.w;
    float ss = h.x * h.x + h.y * h.y + h.z * h.z + h.w * h.w;
    #pragma unroll
    for (int off = 16; off > 0; off >>= 1) {
        s += __shfl_xor_sync(0xffffffff, s, off);
        ss += __shfl_xor_sync(0xffffffff, ss, off);
    }
    const float mean = s * (1.f / HDIM);
    const float var = ss * (1.f / HDIM) - mean * mean;
    const float inv = rsqrtf(var + LN_EPS);

    float4 g = *(const float4*)(gamma + c);
    float4 b = *(const float4*)(beta + c);
    float4 o;
    o.x = g.x * (h.x - mean) * inv + b.x;
    o.y = g.y * (h.y - mean) * inv + b.y;
    o.z = g.z * (h.z - mean) * inv + b.z;
    o.w = g.w * (h.w - mean) * inv + b.w;
    *(float4*)(out + (size_t)gwarp * HDIM + c) = o;
}

// ---------------------------------------------------------------------------
extern "C" void kernel_launch(void* const* d_in, const int* in_sizes, int n_in,
                              void* d_out, int out_size) {
    const float* x         = (const float*)d_in[0];
    const int*   senders   = (const int*)d_in[1];
    const int*   receivers = (const int*)d_in[2];
    const float* ef        = (const float*)d_in[3];
    const float* W1        = (const float*)d_in[4];
    const float* b1        = (const float*)d_in[5];
    const float* gamma     = (const float*)d_in[6];
    const float* beta      = (const float*)d_in[7];
    float* out = (float*)d_out;

    void* aggr_ptr = nullptr;
    cudaGetSymbolAddress(&aggr_ptr, g_aggr);
    cudaMemsetAsync(aggr_ptr, 0, (size_t)N_NODES * HDIM * sizeof(float), 0);

    const size_t smem_np = (size_t)(32768 + 128 * SAW) * sizeof(float);           // ~199 KB
    const size_t smem_ed = (size_t)(128 + 16384 + 2 * 128 * SAW) * sizeof(float); // ~201 KB
    cudaFuncSetAttribute(nodeproj_kernel, cudaFuncAttributeMaxDynamicSharedMemorySize, (int)smem_np);
    cudaFuncSetAttribute(edge_kernel, cudaFuncAttributeMaxDynamicSharedMemorySize, (int)smem_ed);

    nodeproj_kernel<<<148, 512, smem_np>>>(x, W1);
    edge_kernel<<<148, 512, smem_ed>>>(ef, senders, receivers, W1, b1);
    ln_kernel<<<(N_NODES + 7) / 8, 256>>>(x, gamma, beta, out);
}

// round 9
// speedup vs baseline: 2.0411x; 1.0817x over previous
#include <cuda_runtime.h>
#include <cuda_bf16.h>
#include <mma.h>
#include <cstdint>
#include <cstddef>

#define N_NODES 50000
#define N_NODES_PAD 50048          // 391 tiles * 128
#define N_EDGES 800000
#define HDIM 128
#define LN_EPS 1e-5f
#define SAW 132                    // A smem stride in floats (132 % 32 == 4)
#define N_TILES (N_EDGES / 128)
#define NP_TILES ((N_NODES + 127) / 128)

// Scratch (allocation-free rule: __device__ globals)
__device__ float g_xsxr[(size_t)N_NODES_PAD * 256];  // [n,0:128]=x@Ws, [n,128:256]=x@Wr
__device__ float g_aggr[(size_t)N_NODES * HDIM];

__device__ __forceinline__ float t32(float v) { return nvcuda::wmma::__float_to_tf32(v); }

__device__ __forceinline__ void red_add_v2(float* p, float a, float b) {
    asm volatile("red.global.add.v2.f32 [%0], {%1, %2};"
                 :: "l"(p), "f"(a), "f"(b) : "memory");
}

__device__ __forceinline__ void mma_16n8k8(float* c, const uint32_t* a, const uint32_t* b) {
    asm volatile(
        "mma.sync.aligned.m16n8k8.row.col.f32.tf32.tf32.f32 "
        "{%0,%1,%2,%3}, {%4,%5,%6,%7}, {%8,%9}, {%0,%1,%2,%3};"
        : "+f"(c[0]), "+f"(c[1]), "+f"(c[2]), "+f"(c[3])
        : "r"(a[0]), "r"(a[1]), "r"(a[2]), "r"(a[3]), "r"(b[0]), "r"(b[1]));
}

// B fragment-major staging: value (k,n) of a [K=128][n] weight block.
// frag block (ks=k>>3, nt=n>>3) is 64 floats: lane = (n&7)*4 + (k&3), reg = (k&7)>>2.
__device__ __forceinline__ int bfrag_off(int k, int n, int NT) {
    int ks = k >> 3, nt = n >> 3;
    int lane = ((n & 7) << 2) | (k & 3);
    int reg = (k & 7) >> 2;
    return ((ks * NT + nt) << 6) + lane * 2 + reg;
}

// ---------------------------------------------------------------------------
// Node projection (persistent): XsXr[tile] = x[tile] @ [Ws | Wr]
// 512 thr = 16 warps, 2x8 grid of 64x32 warp tiles over 128x256. (unchanged)
// ---------------------------------------------------------------------------
__global__ __launch_bounds__(512, 1)
void nodeproj_kernel(const float* __restrict__ x, const float* __restrict__ W1) {
    extern __shared__ float sm[];
    float* sB = sm;                      // 16 ks * 32 nt * 64 = 32768 floats (frag-major)
    float* sA = sm + 32768;              // 128 x SAW

    const int tid = threadIdx.x;
    const int w = tid >> 5;
    const int lane = tid & 31;
    const int wr = w >> 3;               // 0..1 : 64-row strip
    const int wc = w & 7;                // 0..7 : 32-col strip

    for (int idx = tid; idx < 128 * 256; idx += 512) {
        int k = idx >> 8, n = idx & 255;
        float v = (n < 128) ? W1[(size_t)k * HDIM + n]
                            : W1[(size_t)(128 + k) * HDIM + (n - 128)];
        sB[bfrag_off(k, n, 32)] = t32(v);
    }
    __syncthreads();

    const float2* pB = (const float2*)sB;
    const float* Abase = sA + (wr * 64 + (lane >> 2)) * SAW + (lane & 3);

    for (int t = blockIdx.x; t < NP_TILES; t += gridDim.x) {
        const int rowBase = t * 128;

        for (int idx = tid; idx < 128 * 32; idx += 512) {
            int r = idx >> 5, c4 = idx & 31;
            int gr = rowBase + r;
            float4 v = make_float4(0.f, 0.f, 0.f, 0.f);
            if (gr < N_NODES) v = ((const float4*)(x + (size_t)gr * HDIM))[c4];
            float* d = sA + r * SAW + c4 * 4;
            d[0] = t32(v.x); d[1] = t32(v.y); d[2] = t32(v.z); d[3] = t32(v.w);
        }
        __syncthreads();

        float acc[4][4][4];
        #pragma unroll
        for (int i = 0; i < 4; ++i)
            #pragma unroll
            for (int j = 0; j < 4; ++j)
                acc[i][j][0] = acc[i][j][1] = acc[i][j][2] = acc[i][j][3] = 0.f;

        #pragma unroll
        for (int ks = 0; ks < 16; ++ks) {
            uint32_t a[4][4], b[4][2];
            #pragma unroll
            for (int i = 0; i < 4; ++i) {
                const float* p = Abase + i * (16 * SAW) + ks * 8;
                a[i][0] = __float_as_uint(p[0]);
                a[i][1] = __float_as_uint(p[8 * SAW]);
                a[i][2] = __float_as_uint(p[4]);
                a[i][3] = __float_as_uint(p[8 * SAW + 4]);
            }
            #pragma unroll
            for (int j = 0; j < 4; ++j) {
                float2 bb = pB[(ks * 32 + wc * 4 + j) * 32 + lane];
                b[j][0] = __float_as_uint(bb.x);
                b[j][1] = __float_as_uint(bb.y);
            }
            #pragma unroll
            for (int i = 0; i < 4; ++i)
                #pragma unroll
                for (int j = 0; j < 4; ++j) mma_16n8k8(acc[i][j], a[i], b[j]);
        }

        #pragma unroll
        for (int i = 0; i < 4; ++i) {
            int row = rowBase + wr * 64 + i * 16 + (lane >> 2);
            #pragma unroll
            for (int j = 0; j < 4; ++j) {
                int col = wc * 32 + j * 8 + 2 * (lane & 3);
                *(float2*)(g_xsxr + (size_t)row * 256 + col) =
                    make_float2(acc[i][j][0], acc[i][j][1]);
                *(float2*)(g_xsxr + (size_t)(row + 8) * 256 + col) =
                    make_float2(acc[i][j][2], acc[i][j][3]);
            }
        }
        __syncthreads();
    }
}

// ---------------------------------------------------------------------------
// Fused edge kernel: 512 thr = 2 warpgroups of 8 warps, each wg streams its
// own 128-edge tiles. Per tile: acc := Xs[s]+Xr[r]+b (gather-init, overlaps
// other warps' MMA) ; acc += ef@We (16 tf32 mma ksteps) ; relu ; red.v2 from
// registers. No C/epilogue smem roundtrip; 2 barriers per tile.
// ---------------------------------------------------------------------------
__global__ __launch_bounds__(512, 1)
void edge_kernel(const float* __restrict__ ef,
                 const int* __restrict__ senders,
                 const int* __restrict__ receivers,
                 const float* __restrict__ W1,
                 const float* __restrict__ b1) {
    extern __shared__ float sm[];
    float* sBias = sm;                       // 128
    float* sB  = sm + 128;                   // 16 ks * 16 nt * 64 = 16384 (frag-major)
    float* sA0 = sB + 16384;                 // 128 x SAW (wg0 A)
    float* sA1 = sA0 + 128 * SAW;            // wg1

    const int tid = threadIdx.x;
    const int w = tid >> 5;
    const int lane = tid & 31;
    const int wg = w >> 3;                   // 0/1
    const int wg_tid = tid & 255;
    const int w8 = w & 7;
    const int wr = w8 >> 2;                  // 0..1 : 64-row strip
    const int wc = w8 & 3;                   // 0..3 : 32-col strip
    float* sA = wg ? sA1 : sA0;

    if (tid < 128) sBias[tid] = b1[tid];
    for (int idx = tid; idx < 128 * 128; idx += 512) {
        int k = idx >> 7, n = idx & 127;
        sB[bfrag_off(k, n, 16)] = t32(W1[(size_t)(256 + k) * HDIM + n]);
    }
    __syncthreads();

    const float2* pB = (const float2*)sB;
    const float* Abase = sA + (wr * 64 + (lane >> 2)) * SAW + (lane & 3);
    const int g = lane >> 2;
    const int t2 = 2 * (lane & 3);
    const int barid = wg + 1;

    for (int t = blockIdx.x * 2 + wg; t < N_TILES; t += 2 * gridDim.x) {
        const int base = t * 128;

        // --- stage A: 128 edges x 128 feats (tf32-rounded), 256 threads ---
        const float4* src = (const float4*)(ef + (size_t)t * (128 * HDIM));
        #pragma unroll
        for (int i = 0; i < 16; ++i) {
            int f = i * 256 + wg_tid;
            int r = f >> 5, c4 = f & 31;
            float4 v = src[f];
            float* d = sA + r * SAW + c4 * 4;
            d[0] = t32(v.x); d[1] = t32(v.y); d[2] = t32(v.z); d[3] = t32(v.w);
        }
        asm volatile("bar.sync %0, 256;" :: "r"(barid) : "memory");

        // --- edge indices for this thread's 8 rows ---
        int sarr[8], rarr[8];
        #pragma unroll
        for (int i = 0; i < 4; ++i) {
            int row = wr * 64 + i * 16 + g;
            sarr[2 * i]     = senders[base + row];
            rarr[2 * i]     = receivers[base + row];
            sarr[2 * i + 1] = senders[base + row + 8];
            rarr[2 * i + 1] = receivers[base + row + 8];
        }

        // --- gather-init acc = Xs[s] + Xr[r] + b (float2 per reg-pair) ---
        float acc[4][4][4];
        #pragma unroll
        for (int i = 0; i < 4; ++i) {
            #pragma unroll
            for (int h = 0; h < 2; ++h) {
                const float* xsp = g_xsxr + (size_t)sarr[2 * i + h] * 256;
                const float* xrp = g_xsxr + (size_t)rarr[2 * i + h] * 256 + 128;
                #pragma unroll
                for (int j = 0; j < 4; ++j) {
                    int col = wc * 32 + j * 8 + t2;
                    float2 a_ = *(const float2*)(xsp + col);
                    float2 b_ = *(const float2*)(xrp + col);
                    float2 bb = *(const float2*)(sBias + col);
                    acc[i][j][2 * h]     = a_.x + b_.x + bb.x;
                    acc[i][j][2 * h + 1] = a_.y + b_.y + bb.y;
                }
            }
        }

        // --- acc += ef_tile @ We : 16 tf32 ksteps, 64x32 per warp ---
        #pragma unroll
        for (int ks = 0; ks < 16; ++ks) {
            uint32_t a[4][4], b[4][2];
            #pragma unroll
            for (int i = 0; i < 4; ++i) {
                const float* p = Abase + i * (16 * SAW) + ks * 8;
                a[i][0] = __float_as_uint(p[0]);
                a[i][1] = __float_as_uint(p[8 * SAW]);
                a[i][2] = __float_as_uint(p[4]);
                a[i][3] = __float_as_uint(p[8 * SAW + 4]);
            }
            #pragma unroll
            for (int j = 0; j < 4; ++j) {
                float2 bb = pB[(ks * 16 + wc * 4 + j) * 32 + lane];
                b[j][0] = __float_as_uint(bb.x);
                b[j][1] = __float_as_uint(bb.y);
            }
            #pragma unroll
            for (int i = 0; i < 4; ++i)
                #pragma unroll
                for (int j = 0; j < 4; ++j) mma_16n8k8(acc[i][j], a[i], b[j]);
        }

        // --- relu + scatter straight from acc regs ---
        #pragma unroll
        for (int i = 0; i < 4; ++i) {
            #pragma unroll
            for (int h = 0; h < 2; ++h) {
                float* dst = g_aggr + (size_t)rarr[2 * i + h] * HDIM;
                #pragma unroll
                for (int j = 0; j < 4; ++j) {
                    int col = wc * 32 + j * 8 + t2;
                    float v0 = fmaxf(acc[i][j][2 * h], 0.f);
                    float v1 = fmaxf(acc[i][j][2 * h + 1], 0.f);
                    red_add_v2(dst + col, v0, v1);
                }
            }
        }
        asm volatile("bar.sync %0, 256;" :: "r"(barid) : "memory");  // frag reads done before restage
    }
}

// ---------------------------------------------------------------------------
// LayerNorm: out = gamma * (h - mu) * rsqrt(var + eps) + beta, h = aggr + x
// ---------------------------------------------------------------------------
__global__ __launch_bounds__(256)
void ln_kernel(const float* __restrict__ x,
               const float* __restrict__ gamma,
               const float* __restrict__ beta,
               float* __restrict__ out) {
    const int gwarp = (blockIdx.x * blockDim.x + threadIdx.x) >> 5;
    const int lane = threadIdx.x & 31;
    if (gwarp >= N_NODES) return;

    const int c = lane * 4;
    float4 ag = *(const float4*)(g_aggr + (size_t)gwarp * HDIM + c);
    float4 xv = *(const float4*)(x + (size_t)gwarp * HDIM + c);
    float4 h = make_float4(ag.x + xv.x, ag.y + xv.y, ag.z + xv.z, ag.w + xv.w);

    float s = h.x + h.y + h.z + h.w;
    float ss = h.x * h.x + h.y * h.y + h.z * h.z + h.w * h.w;
    #pragma unroll
    for (int off = 16; off > 0; off >>= 1) {
        s += __shfl_xor_sync(0xffffffff, s, off);
        ss += __shfl_xor_sync(0xffffffff, ss, off);
    }
    const float mean = s * (1.f / HDIM);
    const float var = ss * (1.f / HDIM) - mean * mean;
    const float inv = rsqrtf(var + LN_EPS);

    float4 g = *(const float4*)(gamma + c);
    float4 b = *(const float4*)(beta + c);
    float4 o;
    o.x = g.x * (h.x - mean) * inv + b.x;
    o.y = g.y * (h.y - mean) * inv + b.y;
    o.z = g.z * (h.z - mean) * inv + b.z;
    o.w = g.w * (h.w - mean) * inv + b.w;
    *(float4*)(out + (size_t)gwarp * HDIM + c) = o;
}

// ---------------------------------------------------------------------------
extern "C" void kernel_launch(void* const* d_in, const int* in_sizes, int n_in,
                              void* d_out, int out_size) {
    const float* x         = (const float*)d_in[0];
    const int*   senders   = (const int*)d_in[1];
    const int*   receivers = (const int*)d_in[2];
    const float* ef        = (const float*)d_in[3];
    const float* W1        = (const float*)d_in[4];
    const float* b1        = (const float*)d_in[5];
    const float* gamma     = (const float*)d_in[6];
    const float* beta      = (const float*)d_in[7];
    float* out = (float*)d_out;

    void* aggr_ptr = nullptr;
    cudaGetSymbolAddress(&aggr_ptr, g_aggr);
    cudaMemsetAsync(aggr_ptr, 0, (size_t)N_NODES * HDIM * sizeof(float), 0);

    const size_t smem_np = (size_t)(32768 + 128 * SAW) * sizeof(float);           // ~199 KB
    const size_t smem_ed = (size_t)(128 + 16384 + 2 * 128 * SAW) * sizeof(float); // ~201 KB
    cudaFuncSetAttribute(nodeproj_kernel, cudaFuncAttributeMaxDynamicSharedMemorySize, (int)smem_np);
    cudaFuncSetAttribute(edge_kernel, cudaFuncAttributeMaxDynamicSharedMemorySize, (int)smem_ed);

    nodeproj_kernel<<<148, 512, smem_np>>>(x, W1);
    edge_kernel<<<148, 512, smem_ed>>>(ef, senders, receivers, W1, b1);
    ln_kernel<<<(N_NODES + 7) / 8, 256>>>(x, gamma, beta, out);
}

// round 10
// speedup vs baseline: 3.3084x; 1.6209x over previous
#include <cuda_runtime.h>
#include <cuda_bf16.h>
#include <mma.h>
#include <cstdint>
#include <cstddef>

#define N_NODES 50000
#define N_NODES_PAD 50048          // 391 tiles * 128
#define N_EDGES 800000
#define HDIM 128
#define LN_EPS 1e-5f
#define SAW 132                    // nodeproj A smem stride in floats (132 % 32 == 4)
#define N_TILES (N_EDGES / 128)
#define NP_TILES ((N_NODES + 127) / 128)

// Scratch (allocation-free rule: __device__ globals)
__device__ float g_xsxr[(size_t)N_NODES_PAD * 256];  // [n,0:128]=x@Ws, [n,128:256]=x@Wr
__device__ float g_aggr[(size_t)N_NODES * HDIM];

__device__ __forceinline__ float t32(float v) { return nvcuda::wmma::__float_to_tf32(v); }

__device__ __forceinline__ void red_add_v2(float* p, float a, float b) {
    asm volatile("red.global.add.v2.f32 [%0], {%1, %2};"
                 :: "l"(p), "f"(a), "f"(b) : "memory");
}

__device__ __forceinline__ void mma_16n8k8(float* c, const uint32_t* a, const uint32_t* b) {
    asm volatile(
        "mma.sync.aligned.m16n8k8.row.col.f32.tf32.tf32.f32 "
        "{%0,%1,%2,%3}, {%4,%5,%6,%7}, {%8,%9}, {%0,%1,%2,%3};"
        : "+f"(c[0]), "+f"(c[1]), "+f"(c[2]), "+f"(c[3])
        : "r"(a[0]), "r"(a[1]), "r"(a[2]), "r"(a[3]), "r"(b[0]), "r"(b[1]));
}

// B fragment-major staging: value (k,n) of a [K=128][n] weight block.
// frag block (ks=k>>3, nt=n>>3) is 64 floats: lane = (n&7)*4 + (k&3), reg = (k&7)>>2.
__device__ __forceinline__ int bfrag_off(int k, int n, int NT) {
    int ks = k >> 3, nt = n >> 3;
    int lane = ((n & 7) << 2) | (k & 3);
    int reg = (k & 7) >> 2;
    return ((ks * NT + nt) << 6) + lane * 2 + reg;
}

// ---------------------------------------------------------------------------
// Node projection (persistent): XsXr[tile] = x[tile] @ [Ws | Wr]  (unchanged)
// ---------------------------------------------------------------------------
__global__ __launch_bounds__(512, 1)
void nodeproj_kernel(const float* __restrict__ x, const float* __restrict__ W1) {
    extern __shared__ float sm[];
    float* sB = sm;                      // 16 ks * 32 nt * 64 = 32768 floats (frag-major)
    float* sA = sm + 32768;              // 128 x SAW

    const int tid = threadIdx.x;
    const int w = tid >> 5;
    const int lane = tid & 31;
    const int wr = w >> 3;               // 0..1 : 64-row strip
    const int wc = w & 7;                // 0..7 : 32-col strip

    for (int idx = tid; idx < 128 * 256; idx += 512) {
        int k = idx >> 8, n = idx & 255;
        float v = (n < 128) ? W1[(size_t)k * HDIM + n]
                            : W1[(size_t)(128 + k) * HDIM + (n - 128)];
        sB[bfrag_off(k, n, 32)] = t32(v);
    }
    __syncthreads();

    const float2* pB = (const float2*)sB;
    const float* Abase = sA + (wr * 64 + (lane >> 2)) * SAW + (lane & 3);

    for (int t = blockIdx.x; t < NP_TILES; t += gridDim.x) {
        const int rowBase = t * 128;

        for (int idx = tid; idx < 128 * 32; idx += 512) {
            int r = idx >> 5, c4 = idx & 31;
            int gr = rowBase + r;
            float4 v = make_float4(0.f, 0.f, 0.f, 0.f);
            if (gr < N_NODES) v = ((const float4*)(x + (size_t)gr * HDIM))[c4];
            float* d = sA + r * SAW + c4 * 4;
            d[0] = t32(v.x); d[1] = t32(v.y); d[2] = t32(v.z); d[3] = t32(v.w);
        }
        __syncthreads();

        float acc[4][4][4];
        #pragma unroll
        for (int i = 0; i < 4; ++i)
            #pragma unroll
            for (int j = 0; j < 4; ++j)
                acc[i][j][0] = acc[i][j][1] = acc[i][j][2] = acc[i][j][3] = 0.f;

        #pragma unroll
        for (int ks = 0; ks < 16; ++ks) {
            uint32_t a[4][4], b[4][2];
            #pragma unroll
            for (int i = 0; i < 4; ++i) {
                const float* p = Abase + i * (16 * SAW) + ks * 8;
                a[i][0] = __float_as_uint(p[0]);
                a[i][1] = __float_as_uint(p[8 * SAW]);
                a[i][2] = __float_as_uint(p[4]);
                a[i][3] = __float_as_uint(p[8 * SAW + 4]);
            }
            #pragma unroll
            for (int j = 0; j < 4; ++j) {
                float2 bb = pB[(ks * 32 + wc * 4 + j) * 32 + lane];
                b[j][0] = __float_as_uint(bb.x);
                b[j][1] = __float_as_uint(bb.y);
            }
            #pragma unroll
            for (int i = 0; i < 4; ++i)
                #pragma unroll
                for (int j = 0; j < 4; ++j) mma_16n8k8(acc[i][j], a[i], b[j]);
        }

        #pragma unroll
        for (int i = 0; i < 4; ++i) {
            int row = rowBase + wr * 64 + i * 16 + (lane >> 2);
            #pragma unroll
            for (int j = 0; j < 4; ++j) {
                int col = wc * 32 + j * 8 + 2 * (lane & 3);
                *(float2*)(g_xsxr + (size_t)row * 256 + col) =
                    make_float2(acc[i][j][0], acc[i][j][1]);
                *(float2*)(g_xsxr + (size_t)(row + 8) * 256 + col) =
                    make_float2(acc[i][j][2], acc[i][j][3]);
            }
        }
        __syncthreads();
    }
}

// ---------------------------------------------------------------------------
// Fused edge kernel, barrier-free: 256 thr = 8 independent warps, warp tile
// 32 edges x 64 cols. A fragments loaded straight from global ef (rows owned
// per warp, L1 catches the 2x col-half reuse), B (We frag-major) + bias in
// smem (66 KB -> 2 CTAs/SM). Per tile & warp:
//   acc := Xs[s]+Xr[r]+b  ->  acc += ef@We (16 tf32 ksteps)  ->  relu -> red.v2
// No bar.sync in the main loop: warps' LDG/LDS/HMMA/RED phases interleave.
// ---------------------------------------------------------------------------
__global__ __launch_bounds__(256, 2)
void edge_kernel(const float* __restrict__ ef,
                 const int* __restrict__ senders,
                 const int* __restrict__ receivers,
                 const float* __restrict__ W1,
                 const float* __restrict__ b1) {
    extern __shared__ float sm[];
    float* sBias = sm;                       // 128
    float* sB = sm + 128;                    // 16 ks * 16 nt * 64 = 16384 (frag-major)

    const int tid = threadIdx.x;
    const int w = tid >> 5;
    const int lane = tid & 31;
    const int wr = w >> 1;                   // 0..3 : 32-edge strip
    const int wc = w & 1;                    // 0..1 : 64-col half
    const int g = lane >> 2;
    const int tq = lane & 3;
    const int t2 = 2 * tq;

    if (tid < 128) sBias[tid] = b1[tid];
    for (int idx = tid; idx < 128 * 128; idx += 256) {
        int k = idx >> 7, n = idx & 127;
        sB[bfrag_off(k, n, 16)] = t32(W1[(size_t)(256 + k) * HDIM + n]);
    }
    __syncthreads();

    const float2* pB = (const float2*)sB;

    for (int tile = blockIdx.x; tile < N_TILES; tile += gridDim.x) {
        const int base = tile * 128;
        const int row0 = base + wr * 32 + g;

        // edge indices for this thread's 4 rows
        int sarr[4], rarr[4];
        #pragma unroll
        for (int i = 0; i < 2; ++i) {
            sarr[2 * i]     = senders[row0 + i * 16];
            rarr[2 * i]     = receivers[row0 + i * 16];
            sarr[2 * i + 1] = senders[row0 + i * 16 + 8];
            rarr[2 * i + 1] = receivers[row0 + i * 16 + 8];
        }

        // gather-init acc = Xs[s] + Xr[r] + b
        float acc[2][8][4];
        #pragma unroll
        for (int i = 0; i < 2; ++i) {
            #pragma unroll
            for (int h = 0; h < 2; ++h) {
                const float* xsp = g_xsxr + (size_t)sarr[2 * i + h] * 256;
                const float* xrp = g_xsxr + (size_t)rarr[2 * i + h] * 256 + 128;
                #pragma unroll
                for (int j = 0; j < 8; ++j) {
                    int col = wc * 64 + j * 8 + t2;
                    float2 a_ = *(const float2*)(xsp + col);
                    float2 b_ = *(const float2*)(xrp + col);
                    float2 bb = *(const float2*)(sBias + col);
                    acc[i][j][2 * h]     = a_.x + b_.x + bb.x;
                    acc[i][j][2 * h + 1] = a_.y + b_.y + bb.y;
                }
            }
        }

        // acc += ef_tile @ We : A frags straight from global, B from smem
        const float* Ab = ef + (size_t)(base + wr * 32 + g) * HDIM + tq;
        #pragma unroll
        for (int ks = 0; ks < 16; ++ks) {
            uint32_t a[2][4], b[8][2];
            #pragma unroll
            for (int i = 0; i < 2; ++i) {
                const float* p = Ab + i * (16 * HDIM) + ks * 8;
                a[i][0] = __float_as_uint(t32(p[0]));
                a[i][1] = __float_as_uint(t32(p[8 * HDIM]));
                a[i][2] = __float_as_uint(t32(p[4]));
                a[i][3] = __float_as_uint(t32(p[8 * HDIM + 4]));
            }
            #pragma unroll
            for (int j = 0; j < 8; ++j) {
                float2 bb = pB[(ks * 16 + wc * 8 + j) * 32 + lane];
                b[j][0] = __float_as_uint(bb.x);
                b[j][1] = __float_as_uint(bb.y);
            }
            #pragma unroll
            for (int i = 0; i < 2; ++i)
                #pragma unroll
                for (int j = 0; j < 8; ++j) mma_16n8k8(acc[i][j], a[i], b[j]);
        }

        // relu + scatter straight from acc regs
        #pragma unroll
        for (int i = 0; i < 2; ++i) {
            #pragma unroll
            for (int h = 0; h < 2; ++h) {
                float* dst = g_aggr + (size_t)rarr[2 * i + h] * HDIM;
                #pragma unroll
                for (int j = 0; j < 8; ++j) {
                    int col = wc * 64 + j * 8 + t2;
                    float v0 = fmaxf(acc[i][j][2 * h], 0.f);
                    float v1 = fmaxf(acc[i][j][2 * h + 1], 0.f);
                    red_add_v2(dst + col, v0, v1);
                }
            }
        }
    }
}

// ---------------------------------------------------------------------------
// LayerNorm: out = gamma * (h - mu) * rsqrt(var + eps) + beta, h = aggr + x
// ---------------------------------------------------------------------------
__global__ __launch_bounds__(256)
void ln_kernel(const float* __restrict__ x,
               const float* __restrict__ gamma,
               const float* __restrict__ beta,
               float* __restrict__ out) {
    const int gwarp = (blockIdx.x * blockDim.x + threadIdx.x) >> 5;
    const int lane = threadIdx.x & 31;
    if (gwarp >= N_NODES) return;

    const int c = lane * 4;
    float4 ag = *(const float4*)(g_aggr + (size_t)gwarp * HDIM + c);
    float4 xv = *(const float4*)(x + (size_t)gwarp * HDIM + c);
    float4 h = make_float4(ag.x + xv.x, ag.y + xv.y, ag.z + xv.z, ag.w + xv.w);

    float s = h.x + h.y + h.z + h.w;
    float ss = h.x * h.x + h.y * h.y + h.z * h.z + h.w * h.w;
    #pragma unroll
    for (int off = 16; off > 0; off >>= 1) {
        s += __shfl_xor_sync(0xffffffff, s, off);
        ss += __shfl_xor_sync(0xffffffff, ss, off);
    }
    const float mean = s * (1.f / HDIM);
    const float var = ss * (1.f / HDIM) - mean * mean;
    const float inv = rsqrtf(var + LN_EPS);

    float4 g = *(const float4*)(gamma + c);
    float4 b = *(const float4*)(beta + c);
    float4 o;
    o.x = g.x * (h.x - mean) * inv + b.x;
    o.y = g.y * (h.y - mean) * inv + b.y;
    o.z = g.z * (h.z - mean) * inv + b.z;
    o.w = g.w * (h.w - mean) * inv + b.w;
    *(float4*)(out + (size_t)gwarp * HDIM + c) = o;
}

// ---------------------------------------------------------------------------
extern "C" void kernel_launch(void* const* d_in, const int* in_sizes, int n_in,
                              void* d_out, int out_size) {
    const float* x         = (const float*)d_in[0];
    const int*   senders   = (const int*)d_in[1];
    const int*   receivers = (const int*)d_in[2];
    const float* ef        = (const float*)d_in[3];
    const float* W1        = (const float*)d_in[4];
    const float* b1        = (const float*)d_in[5];
    const float* gamma     = (const float*)d_in[6];
    const float* beta      = (const float*)d_in[7];
    float* out = (float*)d_out;

    void* aggr_ptr = nullptr;
    cudaGetSymbolAddress(&aggr_ptr, g_aggr);
    cudaMemsetAsync(aggr_ptr, 0, (size_t)N_NODES * HDIM * sizeof(float), 0);

    const size_t smem_np = (size_t)(32768 + 128 * SAW) * sizeof(float);   // ~199 KB
    const size_t smem_ed = (size_t)(128 + 16384) * sizeof(float);         // 66 KB -> 2 CTAs/SM
    cudaFuncSetAttribute(nodeproj_kernel, cudaFuncAttributeMaxDynamicSharedMemorySize, (int)smem_np);
    cudaFuncSetAttribute(edge_kernel, cudaFuncAttributeMaxDynamicSharedMemorySize, (int)smem_ed);

    nodeproj_kernel<<<148, 512, smem_np>>>(x, W1);
    edge_kernel<<<296, 256, smem_ed>>>(ef, senders, receivers, W1, b1);
    ln_kernel<<<(N_NODES + 7) / 8, 256>>>(x, gamma, beta, out);
}